// round 9
// baseline (speedup 1.0000x reference)
#include <cuda_runtime.h>
#include <cstdint>

// Problem constants (bin size is exactly 1.0 in both dims; XL=YL=0).
#define NUM_BINS_X 1024
#define NUM_BINS_Y 1024
#define NUM_NODES  4000000
#define NUM_FILLER 1000000
#define NUM_PHYS   (NUM_NODES - NUM_FILLER)   // 3,000,000 (divisible by 4)
#define NUM_MOVABLE 2500000                   // divisible by 4

#define UNIT_PIN_CAPACITY 2.0f
#define MAX_ADJ 2.5f
#define MIN_ADJ (1.0f / 2.5f)
#define PIN_STRETCH_RATIO 1.414f

// Bin map scratch (4 MB) + 16-float pad: v2/v4 REDs and float2/float4 loads
// with an 8B-aligned base (byl & ~1) can index up to pmap_size+2; padded
// slots only ever receive exact 0.0f adds and are multiplied by 0.0f reads.
#define PMAP_N   (NUM_BINS_X * NUM_BINS_Y)
#define PMAP_PAD 16
__device__ __align__(16) float g_pmap[PMAP_N + PMAP_PAD];

__device__ __forceinline__ void red_v2(float* addr, float v0, float v1) {
    asm volatile("red.global.add.v2.f32 [%0], {%1, %2};"
                 :: "l"(addr), "f"(v0), "f"(v1) : "memory");
}
__device__ __forceinline__ void red_v4(float* addr, float v0, float v1,
                                       float v2, float v3) {
    asm volatile("red.global.add.v4.f32 [%0], {%1, %2, %3, %4};"
                 :: "l"(addr), "f"(v0), "f"(v1), "f"(v2), "f"(v3) : "memory");
}

__device__ __forceinline__ float lane_of(const float4& v, int k) {
    return k == 0 ? v.x : k == 1 ? v.y : k == 2 ? v.z : v.w;
}
__device__ __forceinline__ int lane_of(const int4& v, int k) {
    return k == 0 ? v.x : k == 1 ? v.y : k == 2 ? v.z : v.w;
}

// ---------------------------------------------------------------------------
// Kernel 1: scatter pin density into bins. 4 nodes per thread, vectorized
// input loads. Window is provably <= 3x3 bins (node width < 2.0, bin 1.0).
// The 3 y-bins byl..byl+2 live in the 4 slots at b0 = byl & ~1; one v4 RED
// when 16B aligned, else up to two v2 REDs. Out-of-window slots add exact
// 0.0f (matches reference masking numerics).
// ---------------------------------------------------------------------------
__global__ void __launch_bounds__(256) scatter_kernel(
        const float4* __restrict__ px4,
        const float4* __restrict__ py4,
        const float4* __restrict__ sx4,
        const float4* __restrict__ sy4,
        const int4*   __restrict__ pw4) {
    int t = blockIdx.x * blockDim.x + threadIdx.x;
    if (t >= NUM_PHYS / 4) return;

    float4 px = __ldg(px4 + t);
    float4 py = __ldg(py4 + t);
    float4 vx = __ldg(sx4 + t);
    float4 vy = __ldg(sy4 + t);
    int4   w  = __ldg(pw4 + t);

    #pragma unroll
    for (int k = 0; k < 4; ++k) {
        float sx = lane_of(vx, k);
        float sy = lane_of(vy, k);
        float hx = 0.5f * fmaxf(PIN_STRETCH_RATIO, sx);   // bsx = 1.0
        float hy = 0.5f * fmaxf(PIN_STRETCH_RATIO, sy);
        float cx = lane_of(px, k) + 0.5f * sx;
        float cy = lane_of(py, k) + 0.5f * sy;
        float xmin = cx - hx, xmax = cx + hx;
        float ymin = cy - hy, ymax = cy + hy;

        float dens = (float)lane_of(w, k) / (4.0f * hx * hy);

        int bxl = max(0, min(NUM_BINS_X - 1, (int)floorf(xmin)));
        int byl = max(0, min(NUM_BINS_Y - 1, (int)floorf(ymin)));
        int b0  = byl & ~1;                                // 8B-aligned y base
        bool aligned4 = ((b0 & 3) == 0);                   // 16B-aligned group

        // y overlaps for the 4 slots b0..b0+3 (clipped to >= 0).
        float oy0 = fmaxf(fminf(ymax, (float)(b0 + 1)) - fmaxf(ymin, (float)(b0 + 0)), 0.0f);
        float oy1 = fmaxf(fminf(ymax, (float)(b0 + 2)) - fmaxf(ymin, (float)(b0 + 1)), 0.0f);
        float oy2 = fmaxf(fminf(ymax, (float)(b0 + 3)) - fmaxf(ymin, (float)(b0 + 2)), 0.0f);
        float oy3 = fmaxf(fminf(ymax, (float)(b0 + 4)) - fmaxf(ymin, (float)(b0 + 3)), 0.0f);
        bool pair2 = (oy2 + oy3) > 0.0f;

        #pragma unroll
        for (int di = 0; di < 3; ++di) {
            int bx = bxl + di;
            float bl = (float)bx;
            float ox = fminf(xmax, bl + 1.0f) - fmaxf(xmin, bl);
            if (ox <= 0.0f) continue;                      // bx>=1024 lands here too
            float d = dens * ox;
            float* base = g_pmap + bx * NUM_BINS_Y + b0;
            float v0 = d * oy0, v1 = d * oy1, v2 = d * oy2, v3 = d * oy3;
            if (aligned4) {
                red_v4(base, v0, v1, v2, v3);              // one LTS op / column
            } else {
                red_v2(base, v0, v1);                      // slot byl always nonzero
                if (pair2) red_v2(base + 2, v2, v3);
            }
        }
    }
}

// ---------------------------------------------------------------------------
// Kernel 2: gather adj-weighted overlap per movable node (adj fused in).
// 4 nodes per thread: 12-24 independent in-flight map loads for L2 latency
// hiding; one float4 output store per thread.
// ---------------------------------------------------------------------------
__device__ __forceinline__ float adj_of(float v) {
    return fminf(fmaxf(v * (1.0f / UNIT_PIN_CAPACITY), MIN_ADJ), MAX_ADJ);
}

__device__ __forceinline__ float gather_one(float mx, float my,
                                            float msx, float msy) {
    float xmax = mx + msx;
    float ymax = my + msy;

    int bxl = max(0, min(NUM_BINS_X - 1, (int)floorf(mx)));
    int byl = max(0, min(NUM_BINS_Y - 1, (int)floorf(my)));
    int b0  = byl & ~1;

    float oy0 = fmaxf(fminf(ymax, (float)(b0 + 1)) - fmaxf(my, (float)(b0 + 0)), 0.0f);
    float oy1 = fmaxf(fminf(ymax, (float)(b0 + 2)) - fmaxf(my, (float)(b0 + 1)), 0.0f);
    float oy2 = fmaxf(fminf(ymax, (float)(b0 + 3)) - fmaxf(my, (float)(b0 + 2)), 0.0f);
    float oy3 = fmaxf(fminf(ymax, (float)(b0 + 4)) - fmaxf(my, (float)(b0 + 3)), 0.0f);

    float ox[3];
    const float* rp[3];
    #pragma unroll
    for (int di = 0; di < 3; ++di) {
        int bx = bxl + di;
        float bl = (float)bx;
        ox[di] = fmaxf(fminf(xmax, bl + 1.0f) - fmaxf(mx, bl), 0.0f);
        int row = min(bx, NUM_BINS_X - 1) * NUM_BINS_Y;  // ox==0 masks clamped rows
        rp[di] = g_pmap + row + b0;
    }

    float4 q0, q1, q2;
    if ((b0 & 3) == 0) {
        q0 = __ldg(reinterpret_cast<const float4*>(rp[0]));
        q1 = __ldg(reinterpret_cast<const float4*>(rp[1]));
        q2 = __ldg(reinterpret_cast<const float4*>(rp[2]));
    } else {
        float2 a0 = __ldg(reinterpret_cast<const float2*>(rp[0]));
        float2 a1 = __ldg(reinterpret_cast<const float2*>(rp[1]));
        float2 a2 = __ldg(reinterpret_cast<const float2*>(rp[2]));
        float2 c0 = __ldg(reinterpret_cast<const float2*>(rp[0] + 2));
        float2 c1 = __ldg(reinterpret_cast<const float2*>(rp[1] + 2));
        float2 c2 = __ldg(reinterpret_cast<const float2*>(rp[2] + 2));
        q0 = make_float4(a0.x, a0.y, c0.x, c0.y);
        q1 = make_float4(a1.x, a1.y, c1.x, c1.y);
        q2 = make_float4(a2.x, a2.y, c2.x, c2.y);
    }

    float s0 = oy0 * adj_of(q0.x) + oy1 * adj_of(q0.y)
             + oy2 * adj_of(q0.z) + oy3 * adj_of(q0.w);
    float s1 = oy0 * adj_of(q1.x) + oy1 * adj_of(q1.y)
             + oy2 * adj_of(q1.z) + oy3 * adj_of(q1.w);
    float s2 = oy0 * adj_of(q2.x) + oy1 * adj_of(q2.y)
             + oy2 * adj_of(q2.z) + oy3 * adj_of(q2.w);

    return ox[0] * s0 + ox[1] * s1 + ox[2] * s2;
}

__global__ void __launch_bounds__(256) gather_kernel(
        const float4* __restrict__ mx4,
        const float4* __restrict__ my4,
        const float4* __restrict__ sx4,
        const float4* __restrict__ sy4,
        float4* __restrict__ out4) {
    int t = blockIdx.x * blockDim.x + threadIdx.x;
    if (t >= NUM_MOVABLE / 4) return;

    float4 px = __ldg(mx4 + t);
    float4 py = __ldg(my4 + t);
    float4 vx = __ldg(sx4 + t);
    float4 vy = __ldg(sy4 + t);

    float4 r;
    r.x = gather_one(px.x, py.x, vx.x, vy.x);
    r.y = gather_one(px.y, py.y, vx.y, vy.y);
    r.z = gather_one(px.z, py.z, vx.z, vy.z);
    r.w = gather_one(px.w, py.w, vx.w, vy.w);
    out4[t] = r;
}

// ---------------------------------------------------------------------------
extern "C" void kernel_launch(void* const* d_in, const int* in_sizes, int n_in,
                              void* d_out, int out_size) {
    const float* pos = (const float*)d_in[0];       // 8M floats (x then y)
    const float* nsx = (const float*)d_in[1];       // 4M
    const float* nsy = (const float*)d_in[2];       // 4M
    const int*   pw  = (const int*)  d_in[3];       // 3M int32
    float* out = (float*)d_out;                     // 2.5M floats

    // Zero the bin map via a memset node (full-BW fill).
    void* pmap_ptr = nullptr;
    cudaGetSymbolAddress(&pmap_ptr, g_pmap);
    cudaMemsetAsync(pmap_ptr, 0, (PMAP_N + PMAP_PAD) * sizeof(float));

    const int T = 256;
    scatter_kernel<<<(NUM_PHYS / 4 + T - 1) / T, T>>>(
        (const float4*)pos,
        (const float4*)(pos + NUM_NODES),
        (const float4*)nsx,
        (const float4*)nsy,
        (const int4*)pw);
    gather_kernel<<<(NUM_MOVABLE / 4 + T - 1) / T, T>>>(
        (const float4*)pos,
        (const float4*)(pos + NUM_NODES),
        (const float4*)nsx,
        (const float4*)nsy,
        (float4*)out);
}

// round 15
// speedup vs baseline: 1.1270x; 1.1270x over previous
#include <cuda_runtime.h>
#include <cstdint>

// Problem constants (bin size is exactly 1.0 in both dims; XL=YL=0).
#define NUM_BINS_X 1024
#define NUM_BINS_Y 1024
#define NUM_NODES  4000000
#define NUM_FILLER 1000000
#define NUM_PHYS   (NUM_NODES - NUM_FILLER)   // 3,000,000
#define NUM_MOVABLE 2500000

#define UNIT_PIN_CAPACITY 2.0f
#define MAX_ADJ 2.5f
#define MIN_ADJ (1.0f / 2.5f)
#define PIN_STRETCH_RATIO 1.414f

// Bin map scratch (4 MB) + 16-float pad: v2/v4 REDs and float2 loads with an
// 8B-aligned base (byl & ~1) can index up to pmap_size+2; padded slots only
// ever receive exact 0.0f adds and are multiplied by 0.0f reads.
#define PMAP_N   (NUM_BINS_X * NUM_BINS_Y)
#define PMAP_PAD 16
__device__ __align__(16) float g_pmap[PMAP_N + PMAP_PAD];

// Predicated REDs: execute only when pred != 0 (no branch, no BSSY).
// Predicated-off instances never access memory (address may be OOB).
__device__ __forceinline__ void red_v2_pred(float* addr, float v0, float v1,
                                            int pred) {
    asm volatile("{\n\t"
                 ".reg .pred p;\n\t"
                 "setp.ne.s32 p, %0, 0;\n\t"
                 "@p red.global.add.v2.f32 [%1], {%2, %3};\n\t"
                 "}"
                 :: "r"(pred), "l"(addr), "f"(v0), "f"(v1) : "memory");
}
__device__ __forceinline__ void red_v4_pred(float* addr, float v0, float v1,
                                            float v2, float v3, int pred) {
    asm volatile("{\n\t"
                 ".reg .pred p;\n\t"
                 "setp.ne.s32 p, %0, 0;\n\t"
                 "@p red.global.add.v4.f32 [%1], {%2, %3, %4, %5};\n\t"
                 "}"
                 :: "r"(pred), "l"(addr), "f"(v0), "f"(v1), "f"(v2), "f"(v3)
                 : "memory");
}

// Predicated 8B load: executes the LDG only when pred != 0 (no branch, no
// BSSY). Returns (0,0) when predicated off.
__device__ __forceinline__ float2 ldg2_pred(const float* a, int pred) {
    float x = 0.0f, y = 0.0f;
    asm volatile("{\n\t"
                 ".reg .pred p;\n\t"
                 "setp.ne.s32 p, %2, 0;\n\t"
                 "@p ld.global.nc.v2.f32 {%0, %1}, [%3];\n\t"
                 "}"
                 : "+f"(x), "+f"(y) : "r"(pred), "l"(a));
    return make_float2(x, y);
}

// ---------------------------------------------------------------------------
// Kernel 1: scatter pin density into bins. Fully predicated straight-line
// body: per column, one v4 RED (16B-aligned case) or up to two v2 REDs, all
// @p-predicated -- no divergent branches at all. Window is provably <= 3x3
// bins (node width < 2.0, bin 1.0); columns with ox<=0 (incl. bx>=1024) are
// predicated off and never touch memory. Out-of-window slots add exact 0.0f
// (matches reference masking numerics).
// ---------------------------------------------------------------------------
__global__ void __launch_bounds__(256) scatter_kernel(
        const float* __restrict__ pos,
        const float* __restrict__ nsx,
        const float* __restrict__ nsy,
        const int*   __restrict__ pw) {
    int i = blockIdx.x * blockDim.x + threadIdx.x;
    if (i >= NUM_PHYS) return;

    float sx = nsx[i];
    float sy = nsy[i];
    float hx = 0.5f * fmaxf(PIN_STRETCH_RATIO, sx);   // bsx = 1.0
    float hy = 0.5f * fmaxf(PIN_STRETCH_RATIO, sy);
    float cx = pos[i]             + 0.5f * sx;
    float cy = pos[NUM_NODES + i] + 0.5f * sy;
    float xmin = cx - hx, xmax = cx + hx;
    float ymin = cy - hy, ymax = cy + hy;

    float dens = (float)pw[i] / (4.0f * hx * hy);

    int bxl = max(0, min(NUM_BINS_X - 1, (int)floorf(xmin)));
    int byl = max(0, min(NUM_BINS_Y - 1, (int)floorf(ymin)));
    int b0  = byl & ~1;                                // 8B-aligned y base
    int aligned4 = ((b0 & 3) == 0);                    // 16B-aligned group

    // y overlaps for the 4 slots b0..b0+3 (clipped to >= 0).
    float oy0 = fmaxf(fminf(ymax, (float)(b0 + 1)) - fmaxf(ymin, (float)(b0 + 0)), 0.0f);
    float oy1 = fmaxf(fminf(ymax, (float)(b0 + 2)) - fmaxf(ymin, (float)(b0 + 1)), 0.0f);
    float oy2 = fmaxf(fminf(ymax, (float)(b0 + 3)) - fmaxf(ymin, (float)(b0 + 2)), 0.0f);
    float oy3 = fmaxf(fminf(ymax, (float)(b0 + 4)) - fmaxf(ymin, (float)(b0 + 3)), 0.0f);
    int pair2 = (oy2 + oy3) > 0.0f;

    float* base = g_pmap + bxl * NUM_BINS_Y + b0;
    float bl0 = (float)bxl;

    #pragma unroll
    for (int di = 0; di < 3; ++di) {
        // Clipped x overlap; p_col==0 covers both no-overlap and bx>=1024.
        float ox = fminf(xmax, bl0 + (float)(di + 1)) - fmaxf(xmin, bl0 + (float)di);
        int p_col = ox > 0.0f;
        float d = dens * ox;
        float v0 = d * oy0, v1 = d * oy1, v2 = d * oy2, v3 = d * oy3;
        red_v4_pred(base,     v0, v1, v2, v3, p_col &  aligned4);
        red_v2_pred(base,     v0, v1,         p_col & !aligned4);
        red_v2_pred(base + 2, v2, v3,         p_col & !aligned4 & pair2);
        base += NUM_BINS_Y;
    }
}

// ---------------------------------------------------------------------------
// Kernel 2: gather adj-weighted overlap per movable node (adj fused in).
// 1 node/thread. All map loads @p-predicated float2: row 0 pair 1
// unconditional; rows 1-2 predicated on ox>0 (mean live rows 2.25/3);
// pair 2 predicated on (oy2+oy3)>0 (~67%). Predicated-off loads issue no
// memory transaction; no divergent branches at all.
// ---------------------------------------------------------------------------
__device__ __forceinline__ float adj_of(float v) {
    return fminf(fmaxf(v * (1.0f / UNIT_PIN_CAPACITY), MIN_ADJ), MAX_ADJ);
}

__global__ void __launch_bounds__(256) gather_kernel(
        const float* __restrict__ pos,
        const float* __restrict__ nsx,
        const float* __restrict__ nsy,
        float* __restrict__ out) {
    int i = blockIdx.x * blockDim.x + threadIdx.x;
    if (i >= NUM_MOVABLE) return;

    float mx  = pos[i];
    float my  = pos[NUM_NODES + i];
    float xmax = mx + nsx[i];
    float ymax = my + nsy[i];

    int bxl = max(0, min(NUM_BINS_X - 1, (int)floorf(mx)));
    int byl = max(0, min(NUM_BINS_Y - 1, (int)floorf(my)));
    int b0  = byl & ~1;

    float oy0 = fmaxf(fminf(ymax, (float)(b0 + 1)) - fmaxf(my, (float)(b0 + 0)), 0.0f);
    float oy1 = fmaxf(fminf(ymax, (float)(b0 + 2)) - fmaxf(my, (float)(b0 + 1)), 0.0f);
    float oy2 = fmaxf(fminf(ymax, (float)(b0 + 3)) - fmaxf(my, (float)(b0 + 2)), 0.0f);
    float oy3 = fmaxf(fminf(ymax, (float)(b0 + 4)) - fmaxf(my, (float)(b0 + 3)), 0.0f);
    int p_pair2 = (oy2 + oy3) > 0.0f;

    // x overlaps; ox0 > 0 always. ox>0 implies bx <= 1023 (xmax < 1024), so
    // predicated-off rows never need a clamp.
    float bl0 = (float)bxl;
    float ox0 = fminf(xmax, bl0 + 1.0f) - fmaxf(mx, bl0);
    float ox1 = fmaxf(fminf(xmax, bl0 + 2.0f) - fmaxf(mx, bl0 + 1.0f), 0.0f);
    float ox2 = fmaxf(fminf(xmax, bl0 + 3.0f) - fmaxf(mx, bl0 + 2.0f), 0.0f);
    int p_row1 = ox1 > 0.0f;
    int p_row2 = ox2 > 0.0f;

    const float* r0 = g_pmap + bxl * NUM_BINS_Y + b0;
    const float* r1 = r0 + NUM_BINS_Y;
    const float* r2 = r1 + NUM_BINS_Y;

    // Issue all (predicated) loads back-to-back for MLP.
    float2 a0  = ldg2_pred(r0,     1);
    float2 b0v = ldg2_pred(r0 + 2, p_pair2);
    float2 a1  = ldg2_pred(r1,     p_row1);
    float2 b1v = ldg2_pred(r1 + 2, p_row1 & p_pair2);
    float2 a2  = ldg2_pred(r2,     p_row2);
    float2 b2v = ldg2_pred(r2 + 2, p_row2 & p_pair2);

    float s0 = oy0 * adj_of(a0.x) + oy1 * adj_of(a0.y)
             + oy2 * adj_of(b0v.x) + oy3 * adj_of(b0v.y);
    float s1 = oy0 * adj_of(a1.x) + oy1 * adj_of(a1.y)
             + oy2 * adj_of(b1v.x) + oy3 * adj_of(b1v.y);
    float s2 = oy0 * adj_of(a2.x) + oy1 * adj_of(a2.y)
             + oy2 * adj_of(b2v.x) + oy3 * adj_of(b2v.y);

    // Skipped loads return 0 -> adj_of(0) = MIN_ADJ, but the matching ox/oy
    // factor is exactly 0, so the contribution is exactly 0 as in reference.
    out[i] = ox0 * s0 + ox1 * s1 + ox2 * s2;
}

// ---------------------------------------------------------------------------
extern "C" void kernel_launch(void* const* d_in, const int* in_sizes, int n_in,
                              void* d_out, int out_size) {
    const float* pos = (const float*)d_in[0];       // 8M floats (x then y)
    const float* nsx = (const float*)d_in[1];       // 4M
    const float* nsy = (const float*)d_in[2];       // 4M
    const int*   pw  = (const int*)  d_in[3];       // 3M int32
    float* out = (float*)d_out;                     // 2.5M floats

    // Zero the bin map via a memset node (full-BW fill).
    void* pmap_ptr = nullptr;
    cudaGetSymbolAddress(&pmap_ptr, g_pmap);
    cudaMemsetAsync(pmap_ptr, 0, (PMAP_N + PMAP_PAD) * sizeof(float));

    const int T = 256;
    scatter_kernel<<<(NUM_PHYS + T - 1) / T, T>>>(pos, nsx, nsy, pw);
    gather_kernel<<<(NUM_MOVABLE + T - 1) / T, T>>>(pos, nsx, nsy, out);
}

// round 16
// speedup vs baseline: 1.1517x; 1.0220x over previous
#include <cuda_runtime.h>
#include <cstdint>

// Problem constants (bin size is exactly 1.0 in both dims; XL=YL=0).
#define NUM_BINS_X 1024
#define NUM_BINS_Y 1024
#define NUM_NODES  4000000
#define NUM_FILLER 1000000
#define NUM_PHYS   (NUM_NODES - NUM_FILLER)   // 3,000,000
#define NUM_MOVABLE 2500000

#define UNIT_PIN_CAPACITY 2.0f
#define MAX_ADJ 2.5f
#define MIN_ADJ (1.0f / 2.5f)
#define PIN_STRETCH_RATIO 1.414f

// Bin map scratch (4 MB) + 16-float pad: v2/v4 REDs and float2/float4 loads
// with an 8B-aligned base (byl & ~1) can index up to pmap_size+2; padded
// slots only ever receive exact 0.0f adds and are multiplied by 0.0f reads.
#define PMAP_N   (NUM_BINS_X * NUM_BINS_Y)
#define PMAP_PAD 16
__device__ __align__(16) float g_pmap[PMAP_N + PMAP_PAD];

// Predicated REDs: execute only when pred != 0 (no branch, no BSSY).
// Predicated-off instances never access memory (address may be OOB).
__device__ __forceinline__ void red_v2_pred(float* addr, float v0, float v1,
                                            int pred) {
    asm volatile("{\n\t"
                 ".reg .pred p;\n\t"
                 "setp.ne.s32 p, %0, 0;\n\t"
                 "@p red.global.add.v2.f32 [%1], {%2, %3};\n\t"
                 "}"
                 :: "r"(pred), "l"(addr), "f"(v0), "f"(v1) : "memory");
}
__device__ __forceinline__ void red_v4_pred(float* addr, float v0, float v1,
                                            float v2, float v3, int pred) {
    asm volatile("{\n\t"
                 ".reg .pred p;\n\t"
                 "setp.ne.s32 p, %0, 0;\n\t"
                 "@p red.global.add.v4.f32 [%1], {%2, %3, %4, %5};\n\t"
                 "}"
                 :: "r"(pred), "l"(addr), "f"(v0), "f"(v1), "f"(v2), "f"(v3)
                 : "memory");
}

// Predicated 8B load: executes the LDG only when pred != 0 (no branch, no
// BSSY). Returns (0,0) when predicated off.
__device__ __forceinline__ float2 ldg2_pred(const float* a, int pred) {
    float x = 0.0f, y = 0.0f;
    asm volatile("{\n\t"
                 ".reg .pred p;\n\t"
                 "setp.ne.s32 p, %2, 0;\n\t"
                 "@p ld.global.nc.v2.f32 {%0, %1}, [%3];\n\t"
                 "}"
                 : "+f"(x), "+f"(y) : "r"(pred), "l"(a));
    return make_float2(x, y);
}

// Predicated 16B load (requires 16B-aligned address when pred!=0).
__device__ __forceinline__ float4 ldg4_pred(const float* a, int pred) {
    float x = 0.0f, y = 0.0f, z = 0.0f, w = 0.0f;
    asm volatile("{\n\t"
                 ".reg .pred p;\n\t"
                 "setp.ne.s32 p, %4, 0;\n\t"
                 "@p ld.global.nc.v4.f32 {%0, %1, %2, %3}, [%5];\n\t"
                 "}"
                 : "+f"(x), "+f"(y), "+f"(z), "+f"(w) : "r"(pred), "l"(a));
    return make_float4(x, y, z, w);
}

// ---------------------------------------------------------------------------
// Kernel 1: scatter pin density into bins (unchanged from R15: measured at
// its LSU REDG floor). Fully predicated straight-line body: per column, one
// v4 RED (16B-aligned case) or up to two v2 REDs, all @p-predicated.
// Window is provably <= 3x3 bins (node width < 2.0, bin 1.0); columns with
// ox<=0 (incl. bx>=1024) are predicated off and never touch memory.
// Out-of-window slots add exact 0.0f (matches reference masking numerics).
// ---------------------------------------------------------------------------
__global__ void __launch_bounds__(256) scatter_kernel(
        const float* __restrict__ pos,
        const float* __restrict__ nsx,
        const float* __restrict__ nsy,
        const int*   __restrict__ pw) {
    int i = blockIdx.x * blockDim.x + threadIdx.x;
    if (i >= NUM_PHYS) return;

    float sx = nsx[i];
    float sy = nsy[i];
    float hx = 0.5f * fmaxf(PIN_STRETCH_RATIO, sx);   // bsx = 1.0
    float hy = 0.5f * fmaxf(PIN_STRETCH_RATIO, sy);
    float cx = pos[i]             + 0.5f * sx;
    float cy = pos[NUM_NODES + i] + 0.5f * sy;
    float xmin = cx - hx, xmax = cx + hx;
    float ymin = cy - hy, ymax = cy + hy;

    float dens = (float)pw[i] / (4.0f * hx * hy);

    int bxl = max(0, min(NUM_BINS_X - 1, (int)floorf(xmin)));
    int byl = max(0, min(NUM_BINS_Y - 1, (int)floorf(ymin)));
    int b0  = byl & ~1;                                // 8B-aligned y base
    int aligned4 = ((b0 & 3) == 0);                    // 16B-aligned group
    int nal = aligned4 ^ 1;

    // y overlaps for the 4 slots b0..b0+3 (clipped to >= 0).
    float oy0 = fmaxf(fminf(ymax, (float)(b0 + 1)) - fmaxf(ymin, (float)(b0 + 0)), 0.0f);
    float oy1 = fmaxf(fminf(ymax, (float)(b0 + 2)) - fmaxf(ymin, (float)(b0 + 1)), 0.0f);
    float oy2 = fmaxf(fminf(ymax, (float)(b0 + 3)) - fmaxf(ymin, (float)(b0 + 2)), 0.0f);
    float oy3 = fmaxf(fminf(ymax, (float)(b0 + 4)) - fmaxf(ymin, (float)(b0 + 3)), 0.0f);
    int pair2 = (oy2 + oy3) > 0.0f;

    float* base = g_pmap + bxl * NUM_BINS_Y + b0;
    float bl0 = (float)bxl;

    #pragma unroll
    for (int di = 0; di < 3; ++di) {
        // Clipped x overlap; p_col==0 covers both no-overlap and bx>=1024.
        float ox = fminf(xmax, bl0 + (float)(di + 1)) - fmaxf(xmin, bl0 + (float)di);
        int p_col = ox > 0.0f;
        float d = dens * ox;
        float v0 = d * oy0, v1 = d * oy1, v2 = d * oy2, v3 = d * oy3;
        red_v4_pred(base,     v0, v1, v2, v3, p_col & aligned4);
        red_v2_pred(base,     v0, v1,         p_col & nal);
        red_v2_pred(base + 2, v2, v3,         p_col & nal & pair2);
        base += NUM_BINS_Y;
    }
}

// ---------------------------------------------------------------------------
// Kernel 2: gather adj-weighted overlap per movable node (adj fused in).
// Per row: one @p v4 load when the 4-slot group is 16B-aligned, else
// predicated v2 pair -- all branchless, merged by addition (predicated-off
// loads return exact 0.0). Executed spread-load instructions drop from
// ~3.7 to ~3.0 per thread; each such instruction costs one L1tex wavefront
// per lane (random lines), which is the measured bottleneck.
// ---------------------------------------------------------------------------
__device__ __forceinline__ float adj_of(float v) {
    return fminf(fmaxf(v * (1.0f / UNIT_PIN_CAPACITY), MIN_ADJ), MAX_ADJ);
}

__global__ void __launch_bounds__(256) gather_kernel(
        const float* __restrict__ pos,
        const float* __restrict__ nsx,
        const float* __restrict__ nsy,
        float* __restrict__ out) {
    int i = blockIdx.x * blockDim.x + threadIdx.x;
    if (i >= NUM_MOVABLE) return;

    float mx  = pos[i];
    float my  = pos[NUM_NODES + i];
    float xmax = mx + nsx[i];
    float ymax = my + nsy[i];

    int bxl = max(0, min(NUM_BINS_X - 1, (int)floorf(mx)));
    int byl = max(0, min(NUM_BINS_Y - 1, (int)floorf(my)));
    int b0  = byl & ~1;
    int al  = ((b0 & 3) == 0);     // 16B-aligned 4-slot group
    int nal = al ^ 1;

    float oy0 = fmaxf(fminf(ymax, (float)(b0 + 1)) - fmaxf(my, (float)(b0 + 0)), 0.0f);
    float oy1 = fmaxf(fminf(ymax, (float)(b0 + 2)) - fmaxf(my, (float)(b0 + 1)), 0.0f);
    float oy2 = fmaxf(fminf(ymax, (float)(b0 + 3)) - fmaxf(my, (float)(b0 + 2)), 0.0f);
    float oy3 = fmaxf(fminf(ymax, (float)(b0 + 4)) - fmaxf(my, (float)(b0 + 3)), 0.0f);
    int p_pair2 = (oy2 + oy3) > 0.0f;

    // x overlaps; ox0 > 0 always. ox>0 implies bx <= 1023 (xmax < 1024), so
    // predicated-off rows never need a clamp.
    float bl0 = (float)bxl;
    float ox0 = fminf(xmax, bl0 + 1.0f) - fmaxf(mx, bl0);
    float ox1 = fmaxf(fminf(xmax, bl0 + 2.0f) - fmaxf(mx, bl0 + 1.0f), 0.0f);
    float ox2 = fmaxf(fminf(xmax, bl0 + 3.0f) - fmaxf(mx, bl0 + 2.0f), 0.0f);
    int p_row1 = ox1 > 0.0f;
    int p_row2 = ox2 > 0.0f;

    const float* r0 = g_pmap + bxl * NUM_BINS_Y + b0;
    const float* r1 = r0 + NUM_BINS_Y;
    const float* r2 = r1 + NUM_BINS_Y;

    // Per row: v4 (aligned) OR v2+v2 (unaligned), all predicated; merged by
    // addition since predicated-off lanes are exact 0.
    float4 q0 = ldg4_pred(r0, al);
    float2 u0a = ldg2_pred(r0,     nal);
    float2 u0b = ldg2_pred(r0 + 2, nal & p_pair2);
    float4 q1 = ldg4_pred(r1, p_row1 & al);
    float2 u1a = ldg2_pred(r1,     p_row1 & nal);
    float2 u1b = ldg2_pred(r1 + 2, p_row1 & nal & p_pair2);
    float4 q2 = ldg4_pred(r2, p_row2 & al);
    float2 u2a = ldg2_pred(r2,     p_row2 & nal);
    float2 u2b = ldg2_pred(r2 + 2, p_row2 & nal & p_pair2);

    float s0 = oy0 * adj_of(q0.x + u0a.x) + oy1 * adj_of(q0.y + u0a.y)
             + oy2 * adj_of(q0.z + u0b.x) + oy3 * adj_of(q0.w + u0b.y);
    float s1 = oy0 * adj_of(q1.x + u1a.x) + oy1 * adj_of(q1.y + u1a.y)
             + oy2 * adj_of(q1.z + u1b.x) + oy3 * adj_of(q1.w + u1b.y);
    float s2 = oy0 * adj_of(q2.x + u2a.x) + oy1 * adj_of(q2.y + u2a.y)
             + oy2 * adj_of(q2.z + u2b.x) + oy3 * adj_of(q2.w + u2b.y);

    // Fully-skipped slots read 0 -> adj_of(0) = MIN_ADJ, but the matching
    // ox/oy factor is exactly 0, so the contribution is exactly 0 as in the
    // reference's masked adds.
    out[i] = ox0 * s0 + ox1 * s1 + ox2 * s2;
}

// ---------------------------------------------------------------------------
extern "C" void kernel_launch(void* const* d_in, const int* in_sizes, int n_in,
                              void* d_out, int out_size) {
    const float* pos = (const float*)d_in[0];       // 8M floats (x then y)
    const float* nsx = (const float*)d_in[1];       // 4M
    const float* nsy = (const float*)d_in[2];       // 4M
    const int*   pw  = (const int*)  d_in[3];       // 3M int32
    float* out = (float*)d_out;                     // 2.5M floats

    // Zero the bin map via a memset node (full-BW fill).
    void* pmap_ptr = nullptr;
    cudaGetSymbolAddress(&pmap_ptr, g_pmap);
    cudaMemsetAsync(pmap_ptr, 0, (PMAP_N + PMAP_PAD) * sizeof(float));

    const int T = 256;
    scatter_kernel<<<(NUM_PHYS + T - 1) / T, T>>>(pos, nsx, nsy, pw);
    gather_kernel<<<(NUM_MOVABLE + T - 1) / T, T>>>(pos, nsx, nsy, out);
}